// round 17
// baseline (speedup 1.0000x reference)
#include <cuda_runtime.h>
#include <cstdint>

// Binarized NAND-conv net. PERSISTENT warp-level work stealing: 444 blocks
// (one resident wave at 3 blocks/SM), each warp loops on an atomic counter
// grabbing 8-image tasks -> the 544-task tail overlaps bulk compute instead
// of running on an idle chip. Mainloop identical to the 45.7us R15 kernel:
// 4 threads/image, register weights, arithmetic L0, ballot load.
//  L0: 1x28x28 ->16x14x14 (T=4)  L1: ->16x7x7  L2: ->16x6x6
//  L3: ->16x3x3  L4: ->16x1x1 (T=64)  L5: ->10 (T=16)
//  bit=1 <=> +1 ; out bit = (#mismatch >= T/2).

#define NTHREADS 256
#define NWARPS 8
#define GRID_BLOCKS 444                // 148 SMs x 3 blocks
#define WPW 196                        // sbits words per warp (8*784/32)
#define NWORDS (NWARPS * WPW)          // 1568
#define S1 53
#define S2 37
#define S3 13
#define FULL 0xFFFFFFFFu

__device__ unsigned int g_task_counter;

__global__ void reset_counter_kernel() { g_task_counter = 0u; }

__device__ __forceinline__ uint32_t nand16(uint64_t a, const uint64_t (&W)[16]) {
    const uint32_t al = (uint32_t)a, ah = (uint32_t)(a >> 32);
    uint32_t acc = 0;
#pragma unroll
    for (int oc = 0; oc < 16; oc++) {
        uint32_t xl = al ^ (uint32_t)W[oc];
        uint32_t xh = ah ^ (uint32_t)(W[oc] >> 32);
        uint32_t D = __popc(xl) + __popc(xh) + 32;
        acc |= (D >> 6) << oc;        // 1 iff mismatches >= 32 (D in [32,96])
    }
    return acc;
}

// L0 cell: 2x2 patch (rows rA,rB, cols cc,cc+1) vs all 16 channels at once.
__device__ __forceinline__ uint32_t cell16(uint32_t rA, uint32_t rB, int cc,
                                           uint32_t W00, uint32_t W01,
                                           uint32_t W02, uint32_t W03) {
    uint32_t m0 = W00 ^ (uint32_t)(((int)(rA << (31 - cc))) >> 31);
    uint32_t m1 = W01 ^ (uint32_t)(((int)(rA << (30 - cc))) >> 31);
    uint32_t m2 = W02 ^ (uint32_t)(((int)(rB << (31 - cc))) >> 31);
    uint32_t m3 = W03 ^ (uint32_t)(((int)(rB << (30 - cc))) >> 31);
    return (m0 & m1) | (m2 & m3) | ((m0 ^ m1) & (m2 ^ m3));
}

__global__ void __launch_bounds__(NTHREADS, 3)
bnn_mnist_kernel(const float* __restrict__ x,
                 const float* __restrict__ w0, const float* __restrict__ w1,
                 const float* __restrict__ w2, const float* __restrict__ w3,
                 const float* __restrict__ w4, const float* __restrict__ w5,
                 float* __restrict__ out, int B)
{
    __shared__ uint32_t sbits[NWORDS + 1];
    __shared__ uint64_t sw_sh[4][16];
    __shared__ uint32_t sw0t[4];
    __shared__ uint32_t sw5s[10];
    __shared__ uint32_t sact1[NWARPS * 8 * S1];
    __shared__ uint32_t sact2[NWARPS * 8 * S2];
    __shared__ uint32_t sact3[NWARPS * 8 * S3];

    const int tid  = threadIdx.x;
    const int lane = tid & 31;
    const int warp = tid >> 5;

    // ---- weight prep (once per persistent block) ----
    if (tid < 64) {
        int L = tid >> 4, oc = tid & 15;
        const float* wp = (L == 0 ? w1 : L == 1 ? w2 : L == 2 ? w3 : w4) + oc * 64;
        uint64_t v = 0;
#pragma unroll
        for (int ic = 0; ic < 16; ic++)
#pragma unroll
            for (int tap = 0; tap < 4; tap++)
                if (wp[ic * 4 + tap] > 0.0f) v |= 1ull << (tap * 16 + ic);
        sw_sh[L][oc] = v;
    } else if (tid < 68) {
        int k = tid - 64;
        uint32_t v = 0;
#pragma unroll
        for (int c = 0; c < 16; c++)
            if (w0[c * 4 + k] > 0.0f) v |= 1u << c;
        sw0t[k] = v;
    } else if (tid < 78) {
        int c = tid - 68;
        uint32_t v = 0;
#pragma unroll
        for (int ic = 0; ic < 16; ic++)
            if (w5[c * 16 + ic] > 0.0f) v |= 1u << ic;
        sw5s[c] = v;
    } else if (tid == 78) {
        sbits[NWORDS] = 0;
    }
    __syncthreads();

    const unsigned ntasks = (unsigned)((B + 7) / 8);
    const int sub  = lane & 3;
    const int wimg = lane >> 2;            // image slot within warp (0..7)
    const int slot = warp * 8 + wimg;      // block-local image slot
    const int bitbase = slot * 784;
    const int row1 = slot * S1;
    const int row2 = slot * S2;
    const int row3 = slot * S3;
    const int sb = warp * WPW;

    const uint32_t W00 = sw0t[0], W01 = sw0t[1], W02 = sw0t[2], W03 = sw0t[3];

    uint64_t W[16];

    // ================= persistent task loop (warp-scoped) =================
    for (;;) {
        unsigned task;
        if (lane == 0) task = atomicAdd(&g_task_counter, 1u);
        task = __shfl_sync(FULL, task, 0);
        if (task >= ntasks) break;

        const int img = (int)task * 8 + wimg;

        // ---- load + binarize this task's 8 images: LDG.32 + ballot ----
        {
            const float* chunk = x + (size_t)task * (8 * 784);
            if ((int)task * 8 + 8 <= B) {
#pragma unroll
                for (int c0 = 0; c0 < 49; c0 += 7) {
                    float v[28];
#pragma unroll
                    for (int u = 0; u < 7; u++)
#pragma unroll
                        for (int q = 0; q < 4; q++)
                            v[u * 4 + q] = chunk[(c0 + u) * 128 + q * 32 + lane];
#pragma unroll
                    for (int u = 0; u < 7; u++)
#pragma unroll
                        for (int q = 0; q < 4; q++) {
                            unsigned bal = __ballot_sync(FULL, v[u * 4 + q] > 0.0f);
                            if (lane == q) sbits[sb + (c0 + u) * 4 + q] = bal;
                        }
                }
            } else {
                const int nfl = B * 784 - (int)task * (8 * 784);
                for (int wdx = 0; wdx < WPW; wdx++) {
                    int f = wdx * 32 + lane;
                    float v = (f < nfl) ? chunk[f] : 0.0f;
                    unsigned bb = __ballot_sync(FULL, v > 0.0f);
                    if (lane == 0) sbits[sb + wdx] = bb;
                }
            }
        }
        __syncwarp();

        // ---- L0+L1: rows dealt {0,4},{1,5},{2,6},{3} ----
#pragma unroll
        for (int k = 0; k < 16; k++) W[k] = sw_sh[0][k];
#pragma unroll
        for (int t = 0; t < 2; t++) {
            const int i = sub + 4 * t;
            if (i < 7) {
                const int r0 = bitbase + 112 * i;
                int bp = r0;
                uint32_t rA0 = __funnelshift_r(sbits[bp >> 5], sbits[(bp >> 5) + 1], bp);
                bp = r0 + 28;
                uint32_t rB0 = __funnelshift_r(sbits[bp >> 5], sbits[(bp >> 5) + 1], bp);
                bp = r0 + 56;
                uint32_t rA1 = __funnelshift_r(sbits[bp >> 5], sbits[(bp >> 5) + 1], bp);
                bp = r0 + 84;
                uint32_t rB1 = __funnelshift_r(sbits[bp >> 5], sbits[(bp >> 5) + 1], bp);
#pragma unroll
                for (int j = 0; j < 7; j++) {
                    const int cc = 4 * j;
                    uint32_t v00 = cell16(rA0, rB0, cc,     W00, W01, W02, W03) & 0xFFFFu;
                    uint32_t v01 = cell16(rA0, rB0, cc + 2, W00, W01, W02, W03) & 0xFFFFu;
                    uint32_t v10 = cell16(rA1, rB1, cc,     W00, W01, W02, W03) & 0xFFFFu;
                    uint32_t v11 = cell16(rA1, rB1, cc + 2, W00, W01, W02, W03) & 0xFFFFu;
                    uint64_t a64 = (uint64_t)(v00 | (v01 << 16))
                                 | ((uint64_t)(v10 | (v11 << 16)) << 32);
                    sact1[row1 + i * 7 + j] = nand16(a64, W);
                }
            }
        }
        __syncwarp();

        // ---- L2: 7x7 -> 6x6; p = sub + 4k (exact cover of 36) ----
#pragma unroll
        for (int k = 0; k < 16; k++) W[k] = sw_sh[1][k];
#pragma unroll
        for (int k = 0; k < 9; k++) {
            const int p = sub + 4 * k;
            const int i = p / 6;
            const int q = row1 + p + i;
            uint64_t a64 = (uint64_t)sact1[q] | ((uint64_t)sact1[q + 1] << 16)
                         | ((uint64_t)sact1[q + 7] << 32) | ((uint64_t)sact1[q + 8] << 48);
            sact2[row2 + p] = nand16(a64, W);
        }
        __syncwarp();

        // ---- L3: 6x6 -> 3x3; p = sub + 4k, guard p<9 ----
#pragma unroll
        for (int k = 0; k < 16; k++) W[k] = sw_sh[2][k];
#pragma unroll
        for (int k = 0; k < 3; k++) {
            const int p = sub + 4 * k;
            if (p < 9) {
                const int i = p / 3;
                const int j = p - 3 * i;
                const int q = row2 + 12 * i + 2 * j;
                uint64_t a64 = (uint64_t)sact2[q] | ((uint64_t)sact2[q + 1] << 16)
                             | ((uint64_t)sact2[q + 6] << 32) | ((uint64_t)sact2[q + 7] << 48);
                sact3[row3 + p] = nand16(a64, W);
            }
        }
        __syncwarp();

        // ---- L4: 4 ocs per sub, merge via shfl_xor OR ----
        uint32_t act4;
        {
            uint64_t a4 = (uint64_t)sact3[row3 + 0] | ((uint64_t)sact3[row3 + 1] << 16)
                        | ((uint64_t)sact3[row3 + 3] << 32) | ((uint64_t)sact3[row3 + 4] << 48);
            uint32_t acc = 0;
#pragma unroll
            for (int m = 0; m < 4; m++) {
                const int oc = sub * 4 + m;
                uint64_t xx = a4 ^ sw_sh[3][oc];
                uint32_t D = __popc((uint32_t)xx) + __popc((uint32_t)(xx >> 32)) + 32;
                acc |= (D >> 6) << oc;
            }
            acc |= __shfl_xor_sync(FULL, acc, 1);
            acc |= __shfl_xor_sync(FULL, acc, 2);
            act4 = acc;
        }

        // ---- L5: classes dealt per sub ----
        if (img < B) {
            float* o = out + (size_t)img * 10;
#pragma unroll
            for (int k = 0; k < 3; k++) {
                const int oc = sub + 4 * k;
                if (oc < 10) {
                    uint32_t D = __popc((act4 ^ sw5s[oc]) & 0xFFFFu);
                    o[oc] = (D >= 8) ? 1.0f : -1.0f;
                }
            }
        }
        __syncwarp();
    }
}

extern "C" void kernel_launch(void* const* d_in, const int* in_sizes, int n_in,
                              void* d_out, int out_size)
{
    const float* x  = (const float*)d_in[0];
    const float* w0 = (const float*)d_in[1];
    const float* w1 = (const float*)d_in[2];
    const float* w2 = (const float*)d_in[3];
    const float* w3 = (const float*)d_in[4];
    const float* w4 = (const float*)d_in[5];
    const float* w5 = (const float*)d_in[6];
    float* out = (float*)d_out;

    int B = in_sizes[0] / 784;

    reset_counter_kernel<<<1, 1>>>();
    bnn_mnist_kernel<<<GRID_BLOCKS, NTHREADS>>>(x, w0, w1, w2, w3, w4, w5, out, B);
}